// round 12
// baseline (speedup 1.0000x reference)
#include <cuda_runtime.h>
#include <cstdint>

#define DIM   1024
#define FEAT  4096
#define NQ    64
#define NB    8
#define KVR   (NB*(FEAT+NQ))   // 33280
#define LROWS (NB*NQ)          // 512

#define KT     32              // k-tile (floats)
#define NKT    (DIM/KT)        // 32
#define APAD   36
#define BPAD   136
#define STG_F   (128*APAD + KT*BPAD)       // 8960  floats / stage (single-B)
#define STGKV_F (128*APAD + 2*KT*BPAD)     // 13312 floats / stage (fused KV)
#define NSTAGE 3
#define KVSTG  2
#define GEMM_SMEM   (NSTAGE*STG_F*4)       // 107520 B (3-stage, single-B)
#define GEMMKV_SMEM (KVSTG*STGKV_F*4)      // 106496 B (2-stage, fused KV, 2 CTA/SM)

#define NSPLIT 4
#define MLSZ (NB*16*64)                    // 8192 (b,h,q) slots per split
#define NSK  4                             // split-K factor for small GEMMs
#define NKT_SK (NKT/NSK)                   // 8 k-tiles per split

__constant__ int c_cb[NSPLIT+1] = {0, 17, 33, 49, 65};

// Scratch (allocation-free rule: __device__ globals)
__device__ float g_kv[(size_t)KVR*DIM];
__device__ float g_k [(size_t)KVR*DIM];
__device__ float g_v [(size_t)KVR*DIM];
__device__ float g_q [(size_t)LROWS*DIM];
__device__ float g_at[(size_t)LROWS*DIM];
__device__ float g_w [(size_t)4*DIM*DIM];        // tf32-rounded Wk,Wv,Wq,Wo
__device__ float g_po[(size_t)NSPLIT*LROWS*DIM]; // attention partial numerators
__device__ float g_sm[NSPLIT*MLSZ];              // partial row max
__device__ float g_sl[NSPLIT*MLSZ];              // partial row sum
__device__ float g_pp[(size_t)NSK*LROWS*DIM];    // split-K partials

// ---------------- helpers ----------------
__device__ __forceinline__ unsigned f2t(float x){
    unsigned u; asm("cvt.rna.tf32.f32 %0, %1;" : "=r"(u) : "f"(x)); return u;
}
__device__ __forceinline__ float f2tf(float x){ return __uint_as_float(f2t(x)); }

__device__ __forceinline__ void mma8(float* c, const unsigned* a, const unsigned* b){
    asm volatile(
      "mma.sync.aligned.m16n8k8.row.col.f32.tf32.tf32.f32 "
      "{%0,%1,%2,%3},{%4,%5,%6,%7},{%8,%9},{%0,%1,%2,%3};"
      : "+f"(c[0]), "+f"(c[1]), "+f"(c[2]), "+f"(c[3])
      : "r"(a[0]), "r"(a[1]), "r"(a[2]), "r"(a[3]), "r"(b[0]), "r"(b[1]));
}
__device__ __forceinline__ void ldsm4(unsigned* r, uint32_t a){
    asm volatile("ldmatrix.sync.aligned.m8n8.x4.shared.b16 {%0,%1,%2,%3}, [%4];"
      : "=r"(r[0]), "=r"(r[1]), "=r"(r[2]), "=r"(r[3]) : "r"(a));
}
__device__ __forceinline__ uint32_t smem_u32(const void* p){
    uint32_t a;
    asm("{.reg .u64 t; cvta.to.shared.u64 t, %1; cvt.u32.u64 %0, t;}" : "=r"(a) : "l"(p));
    return a;
}
__device__ __forceinline__ void cpasync16(uint32_t d, const void* s){
    asm volatile("cp.async.cg.shared.global [%0], [%1], 16;" :: "r"(d), "l"(s));
}
__device__ __forceinline__ void cp_commit(){ asm volatile("cp.async.commit_group;" ::: "memory"); }
__device__ __forceinline__ void cp_wait0(){ asm volatile("cp.async.wait_group 0;" ::: "memory"); }
__device__ __forceinline__ void cp_wait1(){ asm volatile("cp.async.wait_group 1;" ::: "memory"); }

// per-thread ldmatrix A offset (bytes): tile rows/halves per the x4 lane grouping
__device__ __forceinline__ uint32_t ldsm_a_off(int lane){
    return (uint32_t)(((lane & 7) + 8*((lane >> 3) & 1))*APAD + 4*(lane >> 4))*4u;
}

// ---------------- tf32 weight pre-round (all 4 weights, one launch) ----------------
__global__ __launch_bounds__(256) void round_all(
    const float* __restrict__ s0, const float* __restrict__ s1,
    const float* __restrict__ s2, const float* __restrict__ s3,
    float* __restrict__ d)
{
    const int w = blockIdx.x >> 10;
    const float* s = (w==0) ? s0 : (w==1) ? s1 : (w==2) ? s2 : s3;
    const size_t i = ((size_t)(blockIdx.x & 1023)*256 + threadIdx.x)*4;
    float4 v = *(const float4*)(s + i);
    v.x = f2tf(v.x); v.y = f2tf(v.y); v.z = f2tf(v.z); v.w = f2tf(v.w);
    *(float4*)(d + (size_t)w*DIM*DIM + i) = v;
}

// ---------------- LayerNorm (outputs pre-rounded to tf32) ----------------
__global__ __launch_bounds__(256) void ln_kernel(
    const float* __restrict__ feat, const float* __restrict__ lat,
    const float* __restrict__ mw, const float* __restrict__ mb,
    const float* __restrict__ lw, const float* __restrict__ lb)
{
    const int row = blockIdx.x;
    const int b = row / (FEAT+NQ);
    const int i = row - b*(FEAT+NQ);
    const float *src, *w, *bias;
    if (i < FEAT){ src = feat + (size_t)(b*FEAT + i)*DIM; w = mw; bias = mb; }
    else         { src = lat  + (size_t)(b*NQ + (i-FEAT))*DIM; w = lw; bias = lb; }

    const int tid = threadIdx.x;
    float4 x = ((const float4*)src)[tid];
    float s  = x.x + x.y + x.z + x.w;
    float sq = x.x*x.x + x.y*x.y + x.z*x.z + x.w*x.w;

    __shared__ float red[16];
    #pragma unroll
    for (int o = 16; o > 0; o >>= 1){
        s  += __shfl_xor_sync(0xffffffffu, s, o);
        sq += __shfl_xor_sync(0xffffffffu, sq, o);
    }
    const int wid = tid >> 5, lane = tid & 31;
    if (lane == 0){ red[wid] = s; red[8+wid] = sq; }
    __syncthreads();
    if (wid == 0){
        float ts = (lane < 8) ? red[lane]   : 0.f;
        float tq = (lane < 8) ? red[8+lane] : 0.f;
        #pragma unroll
        for (int o = 4; o > 0; o >>= 1){
            ts += __shfl_xor_sync(0xffffffffu, ts, o);
            tq += __shfl_xor_sync(0xffffffffu, tq, o);
        }
        if (lane == 0){ red[0] = ts; red[1] = tq; }
    }
    __syncthreads();
    const float mu   = red[0] * (1.f/DIM);
    const float var  = red[1] * (1.f/DIM) - mu*mu;
    const float rstd = rsqrtf(var + 1e-5f);

    float4 wv = ((const float4*)w)[tid];
    float4 bv = ((const float4*)bias)[tid];
    float4 y;
    y.x = f2tf((x.x - mu)*rstd*wv.x + bv.x);
    y.y = f2tf((x.y - mu)*rstd*wv.y + bv.y);
    y.z = f2tf((x.z - mu)*rstd*wv.z + bv.z);
    y.w = f2tf((x.w - mu)*rstd*wv.w + bv.w);
    ((float4*)(g_kv + (size_t)row*DIM))[tid] = y;
}

// ---------------- fused K+V GEMM: 2-stage pipeline, 2 CTAs/SM, ldmatrix A ----------------
__global__ __launch_bounds__(256, 2) void gemm_kv(
    const float* __restrict__ A,
    const float* __restrict__ Bk, const float* __restrict__ Bv,
    float* __restrict__ Ck, float* __restrict__ Cv)
{
    extern __shared__ float sm[];
    const int tid = threadIdx.x, lane = tid & 31, wid = tid >> 5;
    const int wm = wid & 1, wn = wid >> 1;
    const int g = lane >> 2, tg = lane & 3;
    const int row0 = blockIdx.y * 128, col0 = blockIdx.x * 128;

    const uint32_t sbase = smem_u32(sm);
    const uint32_t aoff = ldsm_a_off(lane) + (uint32_t)(wm*64*APAD)*4u;

    const int ar = tid >> 3, ac = tid & 7;
    const float* asrc[4];
    uint32_t adst[4];
    #pragma unroll
    for (int p = 0; p < 4; ++p){
        int r = p*32 + ar;
        asrc[p] = A + (size_t)(row0 + r)*DIM + ac*4;
        adst[p] = sbase + (uint32_t)(r*APAD + ac*4)*4u;
    }
    const int bk = tid >> 5, bc = tid & 31;
    const float* bksrc0 = Bk + (size_t)bk*DIM + col0 + bc*4;
    const float* bvsrc0 = Bv + (size_t)bk*DIM + col0 + bc*4;
    const uint32_t bkdst0 = sbase + (uint32_t)(128*APAD + bk*BPAD + bc*4)*4u;
    const uint32_t bvdst0 = bkdst0 + (uint32_t)(KT*BPAD)*4u;

    float ak_[4][4][4], av_[4][4][4];
    #pragma unroll
    for (int mi = 0; mi < 4; ++mi)
      #pragma unroll
      for (int ni = 0; ni < 4; ++ni)
        #pragma unroll
        for (int r = 0; r < 4; ++r){ ak_[mi][ni][r] = 0.f; av_[mi][ni][r] = 0.f; }

    // prologue: stage 0 <- kt 0
    #pragma unroll
    for (int p = 0; p < 4; ++p) cpasync16(adst[p], asrc[p]);
    #pragma unroll
    for (int p = 0; p < 4; ++p){
        cpasync16(bkdst0 + (uint32_t)(p*8*BPAD)*4u, bksrc0 + (size_t)(p*8)*DIM);
        cpasync16(bvdst0 + (uint32_t)(p*8*BPAD)*4u, bvsrc0 + (size_t)(p*8)*DIM);
    }
    cp_commit();

    for (int kt = 0; kt < NKT; ++kt){
        const int buf = kt & 1;
        if (kt > 0) __syncthreads();               // all warps done with buf (kt+1)&1
        if (kt + 1 < NKT){
            const uint32_t so = (uint32_t)((kt+1) & 1)*STGKV_F*4u;
            #pragma unroll
            for (int p = 0; p < 4; ++p) cpasync16(adst[p]+so, asrc[p] + (kt+1)*KT);
            #pragma unroll
            for (int p = 0; p < 4; ++p){
                cpasync16(bkdst0+so + (uint32_t)(p*8*BPAD)*4u, bksrc0 + (size_t)((kt+1)*KT + p*8)*DIM);
                cpasync16(bvdst0+so + (uint32_t)(p*8*BPAD)*4u, bvsrc0 + (size_t)((kt+1)*KT + p*8)*DIM);
            }
            cp_commit();
            cp_wait1();
        } else {
            cp_wait0();
        }
        __syncthreads();

        const uint32_t astage = sbase + (uint32_t)buf*STGKV_F*4u;
        const float* bks = sm + (size_t)buf*STGKV_F + 128*APAD;
        const float* bvs = bks + KT*BPAD;
        #pragma unroll
        for (int ks = 0; ks < 4; ++ks){
            const int k0 = ks*8;
            unsigned a[4][4], bfk[4][2], bfv[4][2];
            #pragma unroll
            for (int mi = 0; mi < 4; ++mi)
                ldsm4(a[mi], astage + aoff + (uint32_t)(mi*16*APAD)*4u + (uint32_t)(k0*4));
            #pragma unroll
            for (int ni = 0; ni < 4; ++ni){
                const float* bp = bks + (k0+tg)*BPAD + wn*32 + ni*8 + g;
                bfk[ni][0] = __float_as_uint(bp[0]);
                bfk[ni][1] = __float_as_uint(bp[4*BPAD]);
                const float* vp = bvs + (k0+tg)*BPAD + wn*32 + ni*8 + g;
                bfv[ni][0] = __float_as_uint(vp[0]);
                bfv[ni][1] = __float_as_uint(vp[4*BPAD]);
            }
            #pragma unroll
            for (int mi = 0; mi < 4; ++mi)
              #pragma unroll
              for (int ni = 0; ni < 4; ++ni){
                mma8(ak_[mi][ni], a[mi], bfk[ni]);
                mma8(av_[mi][ni], a[mi], bfv[ni]);
              }
        }
    }

    #pragma unroll
    for (int mi = 0; mi < 4; ++mi){
        #pragma unroll
        for (int r2 = 0; r2 < 2; ++r2){
            const int row = row0 + wm*64 + mi*16 + r2*8 + g;
            float* ckp = Ck + (size_t)row*DIM + col0 + wn*32 + tg*2;
            float* cvp = Cv + (size_t)row*DIM + col0 + wn*32 + tg*2;
            #pragma unroll
            for (int ni = 0; ni < 4; ++ni){
                float2 vk; vk.x = ak_[mi][ni][r2*2]; vk.y = ak_[mi][ni][r2*2+1];
                *(float2*)(ckp + ni*8) = vk;
                float2 vv; vv.x = av_[mi][ni][r2*2]; vv.y = av_[mi][ni][r2*2+1];
                *(float2*)(cvp + ni*8) = vv;
            }
        }
    }
}

// ---------------- split-K tf32 GEMM (Q and O projections): partials ----------------
// grid (8, M/128, NSK); each z computes k-tiles [z*8, z*8+8) -> g_pp[z]
__global__ __launch_bounds__(256) void gemm_sk(
    const float* __restrict__ A, const float* __restrict__ B,
    float* __restrict__ P, int qmode)
{
    extern __shared__ float sm[];
    const int tid = threadIdx.x, lane = tid & 31, wid = tid >> 5;
    const int wm = wid & 1, wn = wid >> 1;
    const int g = lane >> 2, tg = lane & 3;
    const int row0 = blockIdx.y * 128, col0 = blockIdx.x * 128;
    const int kbeg = blockIdx.z * NKT_SK;

    const uint32_t sbase = smem_u32(sm);
    const uint32_t aoff = ldsm_a_off(lane) + (uint32_t)(wm*64*APAD)*4u;

    const int ar = tid >> 3, ac = tid & 7;
    const float* asrc[4];
    uint32_t adst[4];
    #pragma unroll
    for (int p = 0; p < 4; ++p){
        int r = p*32 + ar;
        int grow = row0 + r;
        if (qmode) grow = (grow >> 6)*(FEAT+NQ) + FEAT + (grow & 63);
        asrc[p] = A + (size_t)grow*DIM + (size_t)kbeg*KT + ac*4;
        adst[p] = sbase + (uint32_t)(r*APAD + ac*4)*4u;
    }
    const int bk = tid >> 5, bc = tid & 31;
    const float* bsrc0 = B + (size_t)(kbeg*KT + bk)*DIM + col0 + bc*4;
    const uint32_t bdst0 = sbase + (uint32_t)(128*APAD + bk*BPAD + bc*4)*4u;

    float acc[4][4][4];
    #pragma unroll
    for (int mi = 0; mi < 4; ++mi)
      #pragma unroll
      for (int ni = 0; ni < 4; ++ni)
        #pragma unroll
        for (int r = 0; r < 4; ++r) acc[mi][ni][r] = 0.f;

    #pragma unroll
    for (int pre = 0; pre < 2; ++pre){
        const uint32_t so = (uint32_t)pre*STG_F*4u;
        #pragma unroll
        for (int p = 0; p < 4; ++p) cpasync16(adst[p]+so, asrc[p] + pre*KT);
        #pragma unroll
        for (int p = 0; p < 4; ++p) cpasync16(bdst0+so + (uint32_t)(p*8*BPAD)*4u,
                                              bsrc0 + (size_t)(pre*KT + p*8)*DIM);
        cp_commit();
    }

    for (int kt = 0; kt < NKT_SK; ++kt){
        const int slot = kt % NSTAGE;
        cp_wait1();
        __syncthreads();

        if (kt + 2 < NKT_SK){
            const int ns = (kt+2) % NSTAGE;
            const uint32_t so = (uint32_t)ns*STG_F*4u;
            #pragma unroll
            for (int p = 0; p < 4; ++p) cpasync16(adst[p]+so, asrc[p] + (kt+2)*KT);
            #pragma unroll
            for (int p = 0; p < 4; ++p) cpasync16(bdst0+so + (uint32_t)(p*8*BPAD)*4u,
                                                  bsrc0 + (size_t)((kt+2)*KT + p*8)*DIM);
        }
        cp_commit();

        const uint32_t astage = sbase + (uint32_t)slot*STG_F*4u;
        const float* bs = sm + (size_t)slot*STG_F + 128*APAD;
        #pragma unroll
        for (int ks = 0; ks < 4; ++ks){
            const int k0 = ks*8;
            unsigned a[4][4], bf[4][2];
            #pragma unroll
            for (int mi = 0; mi < 4; ++mi)
                ldsm4(a[mi], astage + aoff + (uint32_t)(mi*16*APAD)*4u + (uint32_t)(k0*4));
            #pragma unroll
            for (int ni = 0; ni < 4; ++ni){
                const float* bp = bs + (k0+tg)*BPAD + wn*32 + ni*8 + g;
                bf[ni][0] = __float_as_uint(bp[0]);
                bf[ni][1] = __float_as_uint(bp[4*BPAD]);
            }
            #pragma unroll
            for (int mi = 0; mi < 4; ++mi)
              #pragma unroll
              for (int ni = 0; ni < 4; ++ni)
                mma8(acc[mi][ni], a[mi], bf[ni]);
        }
    }

    float* Pz = P + (size_t)blockIdx.z*LROWS*DIM;
    #pragma unroll
    for (int mi = 0; mi < 4; ++mi){
        #pragma unroll
        for (int r2 = 0; r2 < 2; ++r2){
            const int row = row0 + wm*64 + mi*16 + r2*8 + g;
            float* cp = Pz + (size_t)row*DIM + col0 + wn*32 + tg*2;
            #pragma unroll
            for (int ni = 0; ni < 4; ++ni){
                float2 v;
                v.x = acc[mi][ni][r2*2];
                v.y = acc[mi][ni][r2*2+1];
                *(float2*)(cp + ni*8) = v;
            }
        }
    }
}

// ---------------- split-K reduce: dst = alpha * sum_z g_pp[z] ----------------
__global__ __launch_bounds__(256) void reduce_sk(float* __restrict__ dst, float alpha)
{
    const size_t i = ((size_t)blockIdx.x*256 + threadIdx.x)*4;
    float4 a = *(const float4*)(g_pp + i);
    #pragma unroll
    for (int z = 1; z < NSK; ++z){
        const float4 b = *(const float4*)(g_pp + (size_t)z*LROWS*DIM + i);
        a.x += b.x; a.y += b.y; a.z += b.z; a.w += b.w;
    }
    a.x *= alpha; a.y *= alpha; a.z *= alpha; a.w *= alpha;
    *(float4*)(dst + i) = a;
}

// ---------------- split-KV flash attention: block (h, b, split) ----------------
__global__ __launch_bounds__(256) void attn_kernel(const int* __restrict__ mask)
{
    __shared__ float Ks[64][68];
    __shared__ float Vs[64][68];
    __shared__ float madd[64];
    __shared__ float alpha_s[64], m_s[64], l_s[64];

    const int h = blockIdx.x, b = blockIdx.y, sp = blockIdx.z;
    const int cbeg = c_cb[sp], cend = c_cb[sp+1];
    const int tid = threadIdx.x, lane = tid & 31, wid = tid >> 5;
    const int wm = wid & 3, wn = wid >> 2;
    const int g = lane >> 2, tg = lane & 3;

    unsigned qf[8][4];
    {
        const float* qp = g_q + (size_t)(b*NQ + wm*16)*DIM + h*64;
        #pragma unroll
        for (int ks = 0; ks < 8; ++ks){
            qf[ks][0] = f2t(qp[(size_t)(g  )*DIM + ks*8+tg  ]);
            qf[ks][1] = f2t(qp[(size_t)(g+8)*DIM + ks*8+tg  ]);
            qf[ks][2] = f2t(qp[(size_t)(g  )*DIM + ks*8+tg+4]);
            qf[ks][3] = f2t(qp[(size_t)(g+8)*DIM + ks*8+tg+4]);
        }
    }
    float o[4][4];
    #pragma unroll
    for (int ni = 0; ni < 4; ++ni)
      #pragma unroll
      for (int r = 0; r < 4; ++r) o[ni][r] = 0.f;

    if (tid < 64){ m_s[tid] = -1e30f; l_s[tid] = 0.f; }
    __syncthreads();

    for (int c = cbeg; c < cend; ++c){
        const size_t rbase = (size_t)(b*(FEAT+NQ) + c*64);
        #pragma unroll
        for (int i = 0; i < 4; ++i){
            int idx = tid + i*256;
            int r = idx >> 4, c4 = (idx & 15) << 2;
            const float4 kk = *(const float4*)(g_k + (rbase+r)*DIM + h*64 + c4);
            Ks[r][c4+0]=f2tf(kk.x); Ks[r][c4+1]=f2tf(kk.y); Ks[r][c4+2]=f2tf(kk.z); Ks[r][c4+3]=f2tf(kk.w);
            const float4 vv = *(const float4*)(g_v + (rbase+r)*DIM + h*64 + c4);
            Vs[r][c4+0]=f2tf(vv.x); Vs[r][c4+1]=f2tf(vv.y); Vs[r][c4+2]=f2tf(vv.z); Vs[r][c4+3]=f2tf(vv.w);
        }
        if (tid < 64)
            madd[tid] = (c < 64) ? (mask[b*FEAT + c*64 + tid] ? 0.f : -1e30f) : 0.f;
        __syncthreads();

        float s[4][4];
        #pragma unroll
        for (int ni = 0; ni < 4; ++ni)
          #pragma unroll
          for (int r = 0; r < 4; ++r) s[ni][r] = 0.f;
        #pragma unroll
        for (int ks = 0; ks < 8; ++ks){
            unsigned bf[4][2];
            #pragma unroll
            for (int ni = 0; ni < 4; ++ni){
                int n = wn*32 + ni*8 + g;
                bf[ni][0] = __float_as_uint(Ks[n][ks*8+tg  ]);
                bf[ni][1] = __float_as_uint(Ks[n][ks*8+tg+4]);
            }
            #pragma unroll
            for (int ni = 0; ni < 4; ++ni) mma8(s[ni], qf[ks], bf[ni]);
        }
        __syncthreads();

        {
            const int r0 = wm*16 + g;
            #pragma unroll
            for (int ni = 0; ni < 4; ++ni){
                int cc = wn*32 + ni*8 + tg*2;
                Ks[r0  ][cc]   = s[ni][0] + madd[cc];
                Ks[r0  ][cc+1] = s[ni][1] + madd[cc+1];
                Ks[r0+8][cc]   = s[ni][2] + madd[cc];
                Ks[r0+8][cc+1] = s[ni][3] + madd[cc+1];
            }
        }
        __syncthreads();

        {
            const int q = tid >> 2, part = tid & 3;
            float pm = -1e30f;
            #pragma unroll
            for (int j = 0; j < 16; ++j) pm = fmaxf(pm, Ks[q][part*16+j]);
            pm = fmaxf(pm, __shfl_xor_sync(0xffffffffu, pm, 1));
            pm = fmaxf(pm, __shfl_xor_sync(0xffffffffu, pm, 2));
            const float mold = m_s[q];
            const float mnew = fmaxf(mold, pm);
            float psum = 0.f;
            #pragma unroll
            for (int j = 0; j < 16; ++j){
                float sv = Ks[q][part*16+j];
                float p  = (sv > -1e29f) ? __expf(sv - mnew) : 0.f;
                Ks[q][part*16+j] = f2tf(p);
                psum += p;
            }
            psum += __shfl_xor_sync(0xffffffffu, psum, 1);
            psum += __shfl_xor_sync(0xffffffffu, psum, 2);
            if (part == 0){
                float al = __expf(mold - mnew);
                alpha_s[q] = al;
                m_s[q]     = mnew;
                l_s[q]     = l_s[q]*al + psum;
            }
        }
        __syncthreads();

        {
            const float al0 = alpha_s[wm*16 + g];
            const float al1 = alpha_s[wm*16 + 8 + g];
            #pragma unroll
            for (int ni = 0; ni < 4; ++ni){
                o[ni][0]*=al0; o[ni][1]*=al0; o[ni][2]*=al1; o[ni][3]*=al1;
            }
            #pragma unroll
            for (int ks = 0; ks < 8; ++ks){
                unsigned pa[4];
                const int r0 = wm*16;
                pa[0] = __float_as_uint(Ks[r0+g  ][ks*8+tg  ]);
                pa[1] = __float_as_uint(Ks[r0+8+g][ks*8+tg  ]);
                pa[2] = __float_as_uint(Ks[r0+g  ][ks*8+tg+4]);
                pa[3] = __float_as_uint(Ks[r0+8+g][ks*8+tg+4]);
                unsigned bf[4][2];
                #pragma unroll
                for (int ni = 0; ni < 4; ++ni){
                    int n = wn*32 + ni*8 + g;
                    bf[ni][0] = __float_as_uint(Vs[ks*8+tg  ][n]);
                    bf[ni][1] = __float_as_uint(Vs[ks*8+tg+4][n]);
                }
                #pragma unroll
                for (int ni = 0; ni < 4; ++ni) mma8(o[ni], pa, bf[ni]);
            }
        }
        __syncthreads();
    }

    // epilogue: write unnormalized numerator + (m,l)
    {
        float* gpo = g_po + (size_t)sp*LROWS*DIM;
        const int r0 = b*NQ + wm*16 + g;
        #pragma unroll
        for (int ni = 0; ni < 4; ++ni){
            int cc = h*64 + wn*32 + ni*8 + tg*2;
            gpo[(size_t)r0*DIM + cc]       = o[ni][0];
            gpo[(size_t)r0*DIM + cc+1]     = o[ni][1];
            gpo[(size_t)(r0+8)*DIM + cc]   = o[ni][2];
            gpo[(size_t)(r0+8)*DIM + cc+1] = o[ni][3];
        }
        if (tid < 64){
            const int off = sp*MLSZ + (b*16 + h)*64 + tid;
            g_sm[off] = m_s[tid];
            g_sl[off] = l_s[tid];
        }
    }
}

// ---------------- combine splits -> g_at (tf32-rounded) ----------------
__global__ __launch_bounds__(256) void combine_kernel(float* __restrict__ dst)
{
    const int r = blockIdx.x;                 // 0..LROWS-1
    const int b = r >> 6, q = r & 63;
    const int tid = threadIdx.x;
    const int h = tid >> 4;
    const int idx = (b*16 + h)*64 + q;

    float m[NSPLIT], l[NSPLIT];
    float mm = -1e30f;
    #pragma unroll
    for (int sp = 0; sp < NSPLIT; ++sp){
        m[sp] = g_sm[sp*MLSZ + idx];
        l[sp] = g_sl[sp*MLSZ + idx];
        mm = fmaxf(mm, m[sp]);
    }
    float w[NSPLIT], lsum = 0.f;
    #pragma unroll
    for (int sp = 0; sp < NSPLIT; ++sp){
        w[sp] = __expf(m[sp] - mm);
        lsum += w[sp]*l[sp];
    }
    const float inv = 1.f / lsum;

    float4 o = make_float4(0.f, 0.f, 0.f, 0.f);
    #pragma unroll
    for (int sp = 0; sp < NSPLIT; ++sp){
        const float4 a = *(const float4*)(g_po + (size_t)sp*LROWS*DIM + (size_t)r*DIM + tid*4);
        o.x += w[sp]*a.x; o.y += w[sp]*a.y; o.z += w[sp]*a.z; o.w += w[sp]*a.w;
    }
    o.x = f2tf(o.x*inv); o.y = f2tf(o.y*inv);
    o.z = f2tf(o.z*inv); o.w = f2tf(o.w*inv);
    *(float4*)(dst + (size_t)r*DIM + tid*4) = o;
}

// ---------------- launch ----------------
extern "C" void kernel_launch(void* const* d_in, const int* in_sizes, int n_in,
                              void* d_out, int out_size)
{
    const float* feat = (const float*)d_in[0];
    const float* lat  = (const float*)d_in[1];
    const int*   msk  = (const int*)  d_in[2];
    const float* mw   = (const float*)d_in[3];
    const float* mb   = (const float*)d_in[4];
    const float* lw   = (const float*)d_in[5];
    const float* lb   = (const float*)d_in[6];
    const float* Wq   = (const float*)d_in[7];
    const float* Wk   = (const float*)d_in[8];
    const float* Wv   = (const float*)d_in[9];
    const float* Wo   = (const float*)d_in[10];
    float* out = (float*)d_out;

    float *p_kv, *p_k, *p_v, *p_q, *p_at, *p_w, *p_pp;
    cudaGetSymbolAddress((void**)&p_kv, g_kv);
    cudaGetSymbolAddress((void**)&p_k,  g_k);
    cudaGetSymbolAddress((void**)&p_v,  g_v);
    cudaGetSymbolAddress((void**)&p_q,  g_q);
    cudaGetSymbolAddress((void**)&p_at, g_at);
    cudaGetSymbolAddress((void**)&p_w,  g_w);
    cudaGetSymbolAddress((void**)&p_pp, g_pp);

    cudaFuncSetAttribute(gemm_sk, cudaFuncAttributeMaxDynamicSharedMemorySize, GEMM_SMEM);
    cudaFuncSetAttribute(gemm_kv, cudaFuncAttributeMaxDynamicSharedMemorySize, GEMMKV_SMEM);

    round_all<<<4096, 256>>>(Wk, Wv, Wq, Wo, p_w);
    ln_kernel<<<KVR, 256>>>(feat, lat, mw, mb, lw, lb);

    dim3 gbig(8, KVR/128);          // x-fastest: 8 n-blocks share A tiles via L2
    gemm_kv<<<gbig, 256, GEMMKV_SMEM>>>(p_kv,
        p_w + 0*(size_t)DIM*DIM, p_w + 1*(size_t)DIM*DIM, p_k, p_v);

    dim3 gsk(8, LROWS/128, NSK);    // 128 CTAs
    const int RB = (LROWS*DIM)/1024;
    gemm_sk<<<gsk, 256, GEMM_SMEM>>>(p_kv, p_w + 2*(size_t)DIM*DIM, p_pp, 1);
    reduce_sk<<<RB, 256>>>(p_q, 0.125f);     // dh^-0.5 folded

    dim3 gattn(16, NB, NSPLIT);
    attn_kernel<<<gattn, 256>>>(msk);
    combine_kernel<<<LROWS, 256>>>(p_at);

    gemm_sk<<<gsk, 256, GEMM_SMEM>>>(p_at, p_w + 3*(size_t)DIM*DIM, p_pp, 0);
    reduce_sk<<<RB, 256>>>(out, 1.0f);
}

// round 13
// speedup vs baseline: 2.4204x; 2.4204x over previous
#include <cuda_runtime.h>
#include <cstdint>

#define DIM   1024
#define FEAT  4096
#define NQ    64
#define NB    8
#define KVR   (NB*(FEAT+NQ))   // 33280
#define LROWS (NB*NQ)          // 512

#define KT     32              // k-tile (floats)
#define NKT    (DIM/KT)        // 32
#define APAD   36
#define BPAD   136
#define STG_F   (128*APAD + KT*BPAD)       // 8960  floats / stage (single-B)
#define STGKV_F (128*APAD + 2*KT*BPAD)     // 13312 floats / stage (fused KV)
#define NSTAGE 3
#define GEMM_SMEM   (NSTAGE*STG_F*4)       // 107520 B
#define GEMMKV_SMEM (NSTAGE*STGKV_F*4)     // 159744 B (3-stage, 1 CTA/SM)

#define NSPLIT 4
#define MLSZ (NB*16*64)                    // 8192 (b,h,q) slots per split
#define NSK  4                             // split-K factor for small GEMMs
#define NKT_SK (NKT/NSK)                   // 8 k-tiles per split

__constant__ int c_cb[NSPLIT+1] = {0, 17, 33, 49, 65};

// Scratch (allocation-free rule: __device__ globals)
__device__ float g_kv[(size_t)KVR*DIM];
__device__ float g_k [(size_t)KVR*DIM];
__device__ float g_v [(size_t)KVR*DIM];
__device__ float g_q [(size_t)LROWS*DIM];
__device__ float g_at[(size_t)LROWS*DIM];
__device__ float g_w [(size_t)4*DIM*DIM];        // tf32-rounded Wk,Wv,Wq,Wo
__device__ float g_po[(size_t)NSPLIT*LROWS*DIM]; // attention partial numerators
__device__ float g_sm[NSPLIT*MLSZ];              // partial row max
__device__ float g_sl[NSPLIT*MLSZ];              // partial row sum
__device__ float g_pp[(size_t)NSK*LROWS*DIM];    // split-K partials

// ---------------- helpers ----------------
__device__ __forceinline__ unsigned f2t(float x){
    unsigned u; asm("cvt.rna.tf32.f32 %0, %1;" : "=r"(u) : "f"(x)); return u;
}
__device__ __forceinline__ float f2tf(float x){ return __uint_as_float(f2t(x)); }

__device__ __forceinline__ void mma8(float* c, const unsigned* a, const unsigned* b){
    asm volatile(
      "mma.sync.aligned.m16n8k8.row.col.f32.tf32.tf32.f32 "
      "{%0,%1,%2,%3},{%4,%5,%6,%7},{%8,%9},{%0,%1,%2,%3};"
      : "+f"(c[0]), "+f"(c[1]), "+f"(c[2]), "+f"(c[3])
      : "r"(a[0]), "r"(a[1]), "r"(a[2]), "r"(a[3]), "r"(b[0]), "r"(b[1]));
}
__device__ __forceinline__ void ldsm4(unsigned* r, uint32_t a){
    asm volatile("ldmatrix.sync.aligned.m8n8.x4.shared.b16 {%0,%1,%2,%3}, [%4];"
      : "=r"(r[0]), "=r"(r[1]), "=r"(r[2]), "=r"(r[3]) : "r"(a));
}
__device__ __forceinline__ uint32_t smem_u32(const void* p){
    uint32_t a;
    asm("{.reg .u64 t; cvta.to.shared.u64 t, %1; cvt.u32.u64 %0, t;}" : "=r"(a) : "l"(p));
    return a;
}
__device__ __forceinline__ void cpasync16(uint32_t d, const void* s){
    asm volatile("cp.async.cg.shared.global [%0], [%1], 16;" :: "r"(d), "l"(s));
}
__device__ __forceinline__ void cp_commit(){ asm volatile("cp.async.commit_group;" ::: "memory"); }
__device__ __forceinline__ void cp_wait1(){ asm volatile("cp.async.wait_group 1;" ::: "memory"); }

// per-thread ldmatrix A offset (bytes): x4 lane grouping -> 16x8 tf32 block
__device__ __forceinline__ uint32_t ldsm_a_off(int lane){
    return (uint32_t)(((lane & 7) + 8*((lane >> 3) & 1))*APAD + 4*(lane >> 4))*4u;
}

// ---------------- tf32 weight pre-round (all 4 weights, one launch) ----------------
__global__ __launch_bounds__(256) void round_all(
    const float* __restrict__ s0, const float* __restrict__ s1,
    const float* __restrict__ s2, const float* __restrict__ s3,
    float* __restrict__ d)
{
    const int w = blockIdx.x >> 10;
    const float* s = (w==0) ? s0 : (w==1) ? s1 : (w==2) ? s2 : s3;
    const size_t i = ((size_t)(blockIdx.x & 1023)*256 + threadIdx.x)*4;
    float4 v = *(const float4*)(s + i);
    v.x = f2tf(v.x); v.y = f2tf(v.y); v.z = f2tf(v.z); v.w = f2tf(v.w);
    *(float4*)(d + (size_t)w*DIM*DIM + i) = v;
}

// ---------------- LayerNorm (outputs pre-rounded to tf32) ----------------
__global__ __launch_bounds__(256) void ln_kernel(
    const float* __restrict__ feat, const float* __restrict__ lat,
    const float* __restrict__ mw, const float* __restrict__ mb,
    const float* __restrict__ lw, const float* __restrict__ lb)
{
    const int row = blockIdx.x;
    const int b = row / (FEAT+NQ);
    const int i = row - b*(FEAT+NQ);
    const float *src, *w, *bias;
    if (i < FEAT){ src = feat + (size_t)(b*FEAT + i)*DIM; w = mw; bias = mb; }
    else         { src = lat  + (size_t)(b*NQ + (i-FEAT))*DIM; w = lw; bias = lb; }

    const int tid = threadIdx.x;
    float4 x = ((const float4*)src)[tid];
    float s  = x.x + x.y + x.z + x.w;
    float sq = x.x*x.x + x.y*x.y + x.z*x.z + x.w*x.w;

    __shared__ float red[16];
    #pragma unroll
    for (int o = 16; o > 0; o >>= 1){
        s  += __shfl_xor_sync(0xffffffffu, s, o);
        sq += __shfl_xor_sync(0xffffffffu, sq, o);
    }
    const int wid = tid >> 5, lane = tid & 31;
    if (lane == 0){ red[wid] = s; red[8+wid] = sq; }
    __syncthreads();
    if (wid == 0){
        float ts = (lane < 8) ? red[lane]   : 0.f;
        float tq = (lane < 8) ? red[8+lane] : 0.f;
        #pragma unroll
        for (int o = 4; o > 0; o >>= 1){
            ts += __shfl_xor_sync(0xffffffffu, ts, o);
            tq += __shfl_xor_sync(0xffffffffu, tq, o);
        }
        if (lane == 0){ red[0] = ts; red[1] = tq; }
    }
    __syncthreads();
    const float mu   = red[0] * (1.f/DIM);
    const float var  = red[1] * (1.f/DIM) - mu*mu;
    const float rstd = rsqrtf(var + 1e-5f);

    float4 wv = ((const float4*)w)[tid];
    float4 bv = ((const float4*)bias)[tid];
    float4 y;
    y.x = f2tf((x.x - mu)*rstd*wv.x + bv.x);
    y.y = f2tf((x.y - mu)*rstd*wv.y + bv.y);
    y.z = f2tf((x.z - mu)*rstd*wv.z + bv.z);
    y.w = f2tf((x.w - mu)*rstd*wv.w + bv.w);
    ((float4*)(g_kv + (size_t)row*DIM))[tid] = y;
}

// ---------------- fused K+V GEMM: 3-stage pipeline, ldmatrix A, 1 CTA/SM ----------------
__global__ __launch_bounds__(256) void gemm_kv(
    const float* __restrict__ A,
    const float* __restrict__ Bk, const float* __restrict__ Bv,
    float* __restrict__ Ck, float* __restrict__ Cv)
{
    extern __shared__ float sm[];
    const int tid = threadIdx.x, lane = tid & 31, wid = tid >> 5;
    const int wm = wid & 1, wn = wid >> 1;
    const int g = lane >> 2, tg = lane & 3;
    const int row0 = blockIdx.y * 128, col0 = blockIdx.x * 128;

    const uint32_t sbase = smem_u32(sm);
    const uint32_t aoff = ldsm_a_off(lane) + (uint32_t)(wm*64*APAD)*4u;

    const int ar = tid >> 3, ac = tid & 7;
    const float* asrc[4];
    uint32_t adst[4];
    #pragma unroll
    for (int p = 0; p < 4; ++p){
        int r = p*32 + ar;
        asrc[p] = A + (size_t)(row0 + r)*DIM + ac*4;
        adst[p] = sbase + (uint32_t)(r*APAD + ac*4)*4u;
    }
    const int bk = tid >> 5, bc = tid & 31;
    const float* bksrc0 = Bk + (size_t)bk*DIM + col0 + bc*4;
    const float* bvsrc0 = Bv + (size_t)bk*DIM + col0 + bc*4;
    const uint32_t bkdst0 = sbase + (uint32_t)(128*APAD + bk*BPAD + bc*4)*4u;
    const uint32_t bvdst0 = bkdst0 + (uint32_t)(KT*BPAD)*4u;

    float ak_[4][4][4], av_[4][4][4];
    #pragma unroll
    for (int mi = 0; mi < 4; ++mi)
      #pragma unroll
      for (int ni = 0; ni < 4; ++ni)
        #pragma unroll
        for (int r = 0; r < 4; ++r){ ak_[mi][ni][r] = 0.f; av_[mi][ni][r] = 0.f; }

    #pragma unroll
    for (int pre = 0; pre < 2; ++pre){
        const uint32_t so = (uint32_t)pre*STGKV_F*4u;
        #pragma unroll
        for (int p = 0; p < 4; ++p) cpasync16(adst[p]+so, asrc[p] + pre*KT);
        #pragma unroll
        for (int p = 0; p < 4; ++p){
            cpasync16(bkdst0+so + (uint32_t)(p*8*BPAD)*4u, bksrc0 + (size_t)(pre*KT + p*8)*DIM);
            cpasync16(bvdst0+so + (uint32_t)(p*8*BPAD)*4u, bvsrc0 + (size_t)(pre*KT + p*8)*DIM);
        }
        cp_commit();
    }

    for (int kt = 0; kt < NKT; ++kt){
        const int slot = kt % NSTAGE;
        cp_wait1();
        __syncthreads();

        if (kt + 2 < NKT){
            const int ns = (kt+2) % NSTAGE;
            const uint32_t so = (uint32_t)ns*STGKV_F*4u;
            #pragma unroll
            for (int p = 0; p < 4; ++p) cpasync16(adst[p]+so, asrc[p] + (kt+2)*KT);
            #pragma unroll
            for (int p = 0; p < 4; ++p){
                cpasync16(bkdst0+so + (uint32_t)(p*8*BPAD)*4u, bksrc0 + (size_t)((kt+2)*KT + p*8)*DIM);
                cpasync16(bvdst0+so + (uint32_t)(p*8*BPAD)*4u, bvsrc0 + (size_t)((kt+2)*KT + p*8)*DIM);
            }
        }
        cp_commit();

        const uint32_t astage = sbase + (uint32_t)slot*STGKV_F*4u;
        const float* bks = sm + (size_t)slot*STGKV_F + 128*APAD;
        const float* bvs = bks + KT*BPAD;
        #pragma unroll
        for (int ks = 0; ks < 4; ++ks){
            const int k0 = ks*8;
            unsigned a[4][4], bfk[4][2], bfv[4][2];
            #pragma unroll
            for (int mi = 0; mi < 4; ++mi)
                ldsm4(a[mi], astage + aoff + (uint32_t)(mi*16*APAD)*4u + (uint32_t)(k0*4));
            #pragma unroll
            for (int ni = 0; ni < 4; ++ni){
                const float* bp = bks + (k0+tg)*BPAD + wn*32 + ni*8 + g;
                bfk[ni][0] = __float_as_uint(bp[0]);
                bfk[ni][1] = __float_as_uint(bp[4*BPAD]);
                const float* vp = bvs + (k0+tg)*BPAD + wn*32 + ni*8 + g;
                bfv[ni][0] = __float_as_uint(vp[0]);
                bfv[ni][1] = __float_as_uint(vp[4*BPAD]);
            }
            #pragma unroll
            for (int mi = 0; mi < 4; ++mi)
              #pragma unroll
              for (int ni = 0; ni < 4; ++ni){
                mma8(ak_[mi][ni], a[mi], bfk[ni]);
                mma8(av_[mi][ni], a[mi], bfv[ni]);
              }
        }
    }

    #pragma unroll
    for (int mi = 0; mi < 4; ++mi){
        #pragma unroll
        for (int r2 = 0; r2 < 2; ++r2){
            const int row = row0 + wm*64 + mi*16 + r2*8 + g;
            float* ckp = Ck + (size_t)row*DIM + col0 + wn*32 + tg*2;
            float* cvp = Cv + (size_t)row*DIM + col0 + wn*32 + tg*2;
            #pragma unroll
            for (int ni = 0; ni < 4; ++ni){
                float2 vk; vk.x = ak_[mi][ni][r2*2]; vk.y = ak_[mi][ni][r2*2+1];
                *(float2*)(ckp + ni*8) = vk;
                float2 vv; vv.x = av_[mi][ni][r2*2]; vv.y = av_[mi][ni][r2*2+1];
                *(float2*)(cvp + ni*8) = vv;
            }
        }
    }
}

// ---------------- split-K tf32 GEMM (Q and O projections): partials ----------------
__global__ __launch_bounds__(256) void gemm_sk(
    const float* __restrict__ A, const float* __restrict__ B,
    float* __restrict__ P, int qmode)
{
    extern __shared__ float sm[];
    const int tid = threadIdx.x, lane = tid & 31, wid = tid >> 5;
    const int wm = wid & 1, wn = wid >> 1;
    const int g = lane >> 2, tg = lane & 3;
    const int row0 = blockIdx.y * 128, col0 = blockIdx.x * 128;
    const int kbeg = blockIdx.z * NKT_SK;

    const uint32_t sbase = smem_u32(sm);
    const uint32_t aoff = ldsm_a_off(lane) + (uint32_t)(wm*64*APAD)*4u;

    const int ar = tid >> 3, ac = tid & 7;
    const float* asrc[4];
    uint32_t adst[4];
    #pragma unroll
    for (int p = 0; p < 4; ++p){
        int r = p*32 + ar;
        int grow = row0 + r;
        if (qmode) grow = (grow >> 6)*(FEAT+NQ) + FEAT + (grow & 63);
        asrc[p] = A + (size_t)grow*DIM + (size_t)kbeg*KT + ac*4;
        adst[p] = sbase + (uint32_t)(r*APAD + ac*4)*4u;
    }
    const int bk = tid >> 5, bc = tid & 31;
    const float* bsrc0 = B + (size_t)(kbeg*KT + bk)*DIM + col0 + bc*4;
    const uint32_t bdst0 = sbase + (uint32_t)(128*APAD + bk*BPAD + bc*4)*4u;

    float acc[4][4][4];
    #pragma unroll
    for (int mi = 0; mi < 4; ++mi)
      #pragma unroll
      for (int ni = 0; ni < 4; ++ni)
        #pragma unroll
        for (int r = 0; r < 4; ++r) acc[mi][ni][r] = 0.f;

    #pragma unroll
    for (int pre = 0; pre < 2; ++pre){
        const uint32_t so = (uint32_t)pre*STG_F*4u;
        #pragma unroll
        for (int p = 0; p < 4; ++p) cpasync16(adst[p]+so, asrc[p] + pre*KT);
        #pragma unroll
        for (int p = 0; p < 4; ++p) cpasync16(bdst0+so + (uint32_t)(p*8*BPAD)*4u,
                                              bsrc0 + (size_t)(pre*KT + p*8)*DIM);
        cp_commit();
    }

    for (int kt = 0; kt < NKT_SK; ++kt){
        const int slot = kt % NSTAGE;
        cp_wait1();
        __syncthreads();

        if (kt + 2 < NKT_SK){
            const int ns = (kt+2) % NSTAGE;
            const uint32_t so = (uint32_t)ns*STG_F*4u;
            #pragma unroll
            for (int p = 0; p < 4; ++p) cpasync16(adst[p]+so, asrc[p] + (kt+2)*KT);
            #pragma unroll
            for (int p = 0; p < 4; ++p) cpasync16(bdst0+so + (uint32_t)(p*8*BPAD)*4u,
                                                  bsrc0 + (size_t)((kt+2)*KT + p*8)*DIM);
        }
        cp_commit();

        const uint32_t astage = sbase + (uint32_t)slot*STG_F*4u;
        const float* bs = sm + (size_t)slot*STG_F + 128*APAD;
        #pragma unroll
        for (int ks = 0; ks < 4; ++ks){
            const int k0 = ks*8;
            unsigned a[4][4], bf[4][2];
            #pragma unroll
            for (int mi = 0; mi < 4; ++mi)
                ldsm4(a[mi], astage + aoff + (uint32_t)(mi*16*APAD)*4u + (uint32_t)(k0*4));
            #pragma unroll
            for (int ni = 0; ni < 4; ++ni){
                const float* bp = bs + (k0+tg)*BPAD + wn*32 + ni*8 + g;
                bf[ni][0] = __float_as_uint(bp[0]);
                bf[ni][1] = __float_as_uint(bp[4*BPAD]);
            }
            #pragma unroll
            for (int mi = 0; mi < 4; ++mi)
              #pragma unroll
              for (int ni = 0; ni < 4; ++ni)
                mma8(acc[mi][ni], a[mi], bf[ni]);
        }
    }

    float* Pz = P + (size_t)blockIdx.z*LROWS*DIM;
    #pragma unroll
    for (int mi = 0; mi < 4; ++mi){
        #pragma unroll
        for (int r2 = 0; r2 < 2; ++r2){
            const int row = row0 + wm*64 + mi*16 + r2*8 + g;
            float* cp = Pz + (size_t)row*DIM + col0 + wn*32 + tg*2;
            #pragma unroll
            for (int ni = 0; ni < 4; ++ni){
                float2 v;
                v.x = acc[mi][ni][r2*2];
                v.y = acc[mi][ni][r2*2+1];
                *(float2*)(cp + ni*8) = v;
            }
        }
    }
}

// ---------------- split-K reduce: dst = alpha * sum_z g_pp[z] ----------------
__global__ __launch_bounds__(256) void reduce_sk(float* __restrict__ dst, float alpha)
{
    const size_t i = ((size_t)blockIdx.x*256 + threadIdx.x)*4;
    float4 a = *(const float4*)(g_pp + i);
    #pragma unroll
    for (int z = 1; z < NSK; ++z){
        const float4 b = *(const float4*)(g_pp + (size_t)z*LROWS*DIM + i);
        a.x += b.x; a.y += b.y; a.z += b.z; a.w += b.w;
    }
    a.x *= alpha; a.y *= alpha; a.z *= alpha; a.w *= alpha;
    *(float4*)(dst + i) = a;
}

// ---------------- split-KV flash attention: block (h, b, split) ----------------
__global__ __launch_bounds__(256) void attn_kernel(const int* __restrict__ mask)
{
    __shared__ float Ks[64][68];
    __shared__ float Vs[64][68];
    __shared__ float madd[64];
    __shared__ float alpha_s[64], m_s[64], l_s[64];

    const int h = blockIdx.x, b = blockIdx.y, sp = blockIdx.z;
    const int cbeg = c_cb[sp], cend = c_cb[sp+1];
    const int tid = threadIdx.x, lane = tid & 31, wid = tid >> 5;
    const int wm = wid & 3, wn = wid >> 2;
    const int g = lane >> 2, tg = lane & 3;

    unsigned qf[8][4];
    {
        const float* qp = g_q + (size_t)(b*NQ + wm*16)*DIM + h*64;
        #pragma unroll
        for (int ks = 0; ks < 8; ++ks){
            qf[ks][0] = f2t(qp[(size_t)(g  )*DIM + ks*8+tg  ]);
            qf[ks][1] = f2t(qp[(size_t)(g+8)*DIM + ks*8+tg  ]);
            qf[ks][2] = f2t(qp[(size_t)(g  )*DIM + ks*8+tg+4]);
            qf[ks][3] = f2t(qp[(size_t)(g+8)*DIM + ks*8+tg+4]);
        }
    }
    float o[4][4];
    #pragma unroll
    for (int ni = 0; ni < 4; ++ni)
      #pragma unroll
      for (int r = 0; r < 4; ++r) o[ni][r] = 0.f;

    if (tid < 64){ m_s[tid] = -1e30f; l_s[tid] = 0.f; }
    __syncthreads();

    for (int c = cbeg; c < cend; ++c){
        const size_t rbase = (size_t)(b*(FEAT+NQ) + c*64);
        #pragma unroll
        for (int i = 0; i < 4; ++i){
            int idx = tid + i*256;
            int r = idx >> 4, c4 = (idx & 15) << 2;
            const float4 kk = *(const float4*)(g_k + (rbase+r)*DIM + h*64 + c4);
            Ks[r][c4+0]=f2tf(kk.x); Ks[r][c4+1]=f2tf(kk.y); Ks[r][c4+2]=f2tf(kk.z); Ks[r][c4+3]=f2tf(kk.w);
            const float4 vv = *(const float4*)(g_v + (rbase+r)*DIM + h*64 + c4);
            Vs[r][c4+0]=f2tf(vv.x); Vs[r][c4+1]=f2tf(vv.y); Vs[r][c4+2]=f2tf(vv.z); Vs[r][c4+3]=f2tf(vv.w);
        }
        if (tid < 64)
            madd[tid] = (c < 64) ? (mask[b*FEAT + c*64 + tid] ? 0.f : -1e30f) : 0.f;
        __syncthreads();

        float s[4][4];
        #pragma unroll
        for (int ni = 0; ni < 4; ++ni)
          #pragma unroll
          for (int r = 0; r < 4; ++r) s[ni][r] = 0.f;
        #pragma unroll
        for (int ks = 0; ks < 8; ++ks){
            unsigned bf[4][2];
            #pragma unroll
            for (int ni = 0; ni < 4; ++ni){
                int n = wn*32 + ni*8 + g;
                bf[ni][0] = __float_as_uint(Ks[n][ks*8+tg  ]);
                bf[ni][1] = __float_as_uint(Ks[n][ks*8+tg+4]);
            }
            #pragma unroll
            for (int ni = 0; ni < 4; ++ni) mma8(s[ni], qf[ks], bf[ni]);
        }
        __syncthreads();

        {
            const int r0 = wm*16 + g;
            #pragma unroll
            for (int ni = 0; ni < 4; ++ni){
                int cc = wn*32 + ni*8 + tg*2;
                Ks[r0  ][cc]   = s[ni][0] + madd[cc];
                Ks[r0  ][cc+1] = s[ni][1] + madd[cc+1];
                Ks[r0+8][cc]   = s[ni][2] + madd[cc];
                Ks[r0+8][cc+1] = s[ni][3] + madd[cc+1];
            }
        }
        __syncthreads();

        {
            const int q = tid >> 2, part = tid & 3;
            float pm = -1e30f;
            #pragma unroll
            for (int j = 0; j < 16; ++j) pm = fmaxf(pm, Ks[q][part*16+j]);
            pm = fmaxf(pm, __shfl_xor_sync(0xffffffffu, pm, 1));
            pm = fmaxf(pm, __shfl_xor_sync(0xffffffffu, pm, 2));
            const float mold = m_s[q];
            const float mnew = fmaxf(mold, pm);
            float psum = 0.f;
            #pragma unroll
            for (int j = 0; j < 16; ++j){
                float sv = Ks[q][part*16+j];
                float p  = (sv > -1e29f) ? __expf(sv - mnew) : 0.f;
                Ks[q][part*16+j] = f2tf(p);
                psum += p;
            }
            psum += __shfl_xor_sync(0xffffffffu, psum, 1);
            psum += __shfl_xor_sync(0xffffffffu, psum, 2);
            if (part == 0){
                float al = __expf(mold - mnew);
                alpha_s[q] = al;
                m_s[q]     = mnew;
                l_s[q]     = l_s[q]*al + psum;
            }
        }
        __syncthreads();

        {
            const float al0 = alpha_s[wm*16 + g];
            const float al1 = alpha_s[wm*16 + 8 + g];
            #pragma unroll
            for (int ni = 0; ni < 4; ++ni){
                o[ni][0]*=al0; o[ni][1]*=al0; o[ni][2]*=al1; o[ni][3]*=al1;
            }
            #pragma unroll
            for (int ks = 0; ks < 8; ++ks){
                unsigned pa[4];
                const int r0 = wm*16;
                pa[0] = __float_as_uint(Ks[r0+g  ][ks*8+tg  ]);
                pa[1] = __float_as_uint(Ks[r0+8+g][ks*8+tg  ]);
                pa[2] = __float_as_uint(Ks[r0+g  ][ks*8+tg+4]);
                pa[3] = __float_as_uint(Ks[r0+8+g][ks*8+tg+4]);
                unsigned bf[4][2];
                #pragma unroll
                for (int ni = 0; ni < 4; ++ni){
                    int n = wn*32 + ni*8 + g;
                    bf[ni][0] = __float_as_uint(Vs[ks*8+tg  ][n]);
                    bf[ni][1] = __float_as_uint(Vs[ks*8+tg+4][n]);
                }
                #pragma unroll
                for (int ni = 0; ni < 4; ++ni) mma8(o[ni], pa, bf[ni]);
            }
        }
        __syncthreads();
    }

    // epilogue: write unnormalized numerator + (m,l)
    {
        float* gpo = g_po + (size_t)sp*LROWS*DIM;
        const int r0 = b*NQ + wm*16 + g;
        #pragma unroll
        for (int ni = 0; ni < 4; ++ni){
            int cc = h*64 + wn*32 + ni*8 + tg*2;
            gpo[(size_t)r0*DIM + cc]       = o[ni][0];
            gpo[(size_t)r0*DIM + cc+1]     = o[ni][1];
            gpo[(size_t)(r0+8)*DIM + cc]   = o[ni][2];
            gpo[(size_t)(r0+8)*DIM + cc+1] = o[ni][3];
        }
        if (tid < 64){
            const int off = sp*MLSZ + (b*16 + h)*64 + tid;
            g_sm[off] = m_s[tid];
            g_sl[off] = l_s[tid];
        }
    }
}

// ---------------- combine splits -> g_at (tf32-rounded) ----------------
__global__ __launch_bounds__(256) void combine_kernel(float* __restrict__ dst)
{
    const int r = blockIdx.x;                 // 0..LROWS-1
    const int b = r >> 6, q = r & 63;
    const int tid = threadIdx.x;
    const int h = tid >> 4;
    const int idx = (b*16 + h)*64 + q;

    float m[NSPLIT], l[NSPLIT];
    float mm = -1e30f;
    #pragma unroll
    for (int sp = 0; sp < NSPLIT; ++sp){
        m[sp] = g_sm[sp*MLSZ + idx];
        l[sp] = g_sl[sp*MLSZ + idx];
        mm = fmaxf(mm, m[sp]);
    }
    float w[NSPLIT], lsum = 0.f;
    #pragma unroll
    for (int sp = 0; sp < NSPLIT; ++sp){
        w[sp] = __expf(m[sp] - mm);
        lsum += w[sp]*l[sp];
    }
    const float inv = 1.f / lsum;

    float4 o = make_float4(0.f, 0.f, 0.f, 0.f);
    #pragma unroll
    for (int sp = 0; sp < NSPLIT; ++sp){
        const float4 a = *(const float4*)(g_po + (size_t)sp*LROWS*DIM + (size_t)r*DIM + tid*4);
        o.x += w[sp]*a.x; o.y += w[sp]*a.y; o.z += w[sp]*a.z; o.w += w[sp]*a.w;
    }
    o.x = f2tf(o.x*inv); o.y = f2tf(o.y*inv);
    o.z = f2tf(o.z*inv); o.w = f2tf(o.w*inv);
    *(float4*)(dst + (size_t)r*DIM + tid*4) = o;
}

// ---------------- launch ----------------
extern "C" void kernel_launch(void* const* d_in, const int* in_sizes, int n_in,
                              void* d_out, int out_size)
{
    const float* feat = (const float*)d_in[0];
    const float* lat  = (const float*)d_in[1];
    const int*   msk  = (const int*)  d_in[2];
    const float* mw   = (const float*)d_in[3];
    const float* mb   = (const float*)d_in[4];
    const float* lw   = (const float*)d_in[5];
    const float* lb   = (const float*)d_in[6];
    const float* Wq   = (const float*)d_in[7];
    const float* Wk   = (const float*)d_in[8];
    const float* Wv   = (const float*)d_in[9];
    const float* Wo   = (const float*)d_in[10];
    float* out = (float*)d_out;

    float *p_kv, *p_k, *p_v, *p_q, *p_at, *p_w, *p_pp;
    cudaGetSymbolAddress((void**)&p_kv, g_kv);
    cudaGetSymbolAddress((void**)&p_k,  g_k);
    cudaGetSymbolAddress((void**)&p_v,  g_v);
    cudaGetSymbolAddress((void**)&p_q,  g_q);
    cudaGetSymbolAddress((void**)&p_at, g_at);
    cudaGetSymbolAddress((void**)&p_w,  g_w);
    cudaGetSymbolAddress((void**)&p_pp, g_pp);

    cudaFuncSetAttribute(gemm_sk, cudaFuncAttributeMaxDynamicSharedMemorySize, GEMM_SMEM);
    cudaFuncSetAttribute(gemm_kv, cudaFuncAttributeMaxDynamicSharedMemorySize, GEMMKV_SMEM);

    round_all<<<4096, 256>>>(Wk, Wv, Wq, Wo, p_w);
    ln_kernel<<<KVR, 256>>>(feat, lat, mw, mb, lw, lb);

    dim3 gbig(8, KVR/128);          // x-fastest: 8 n-blocks share A tiles via L2
    gemm_kv<<<gbig, 256, GEMMKV_SMEM>>>(p_kv,
        p_w + 0*(size_t)DIM*DIM, p_w + 1*(size_t)DIM*DIM, p_k, p_v);

    dim3 gsk(8, LROWS/128, NSK);    // 128 CTAs
    const int RB = (LROWS*DIM)/1024;
    gemm_sk<<<gsk, 256, GEMM_SMEM>>>(p_kv, p_w + 2*(size_t)DIM*DIM, p_pp, 1);
    reduce_sk<<<RB, 256>>>(p_q, 0.125f);     // dh^-0.5 folded

    dim3 gattn(16, NB, NSPLIT);
    attn_kernel<<<gattn, 256>>>(msk);
    combine_kernel<<<LROWS, 256>>>(p_at);

    gemm_sk<<<gsk, 256, GEMM_SMEM>>>(p_at, p_w + 3*(size_t)DIM*DIM, p_pp, 0);
    reduce_sk<<<RB, 256>>>(out, 1.0f);
}